// round 14
// baseline (speedup 1.0000x reference)
#include <cuda_runtime.h>
#include <math.h>

#define HW     90000
#define NPAIR  45000
#define NQUAD  22500
#define CROP   300
#define NHALF  150
#define DH     32
#define EMB    64
#define CHIN   256
#define NPANEL 19     // ceil(300/16)

typedef unsigned long long ull;
typedef unsigned int uint;

// ---- packed fp32x2 helpers ------------------------------------------------
__device__ __forceinline__ ull pack2(float lo, float hi) {
    ull r; asm("mov.b64 %0, {%1, %2};" : "=l"(r) : "f"(lo), "f"(hi)); return r;
}
__device__ __forceinline__ void unpack2(ull v, float& lo, float& hi) {
    asm("mov.b64 {%0, %1}, %2;" : "=f"(lo), "=f"(hi) : "l"(v));
}
__device__ __forceinline__ ull fma2(ull a, ull b, ull c) {
    ull d; asm("fma.rn.f32x2 %0, %1, %2, %3;" : "=l"(d) : "l"(a), "l"(b), "l"(c)); return d;
}

// ---- tf32 helpers ----------------------------------------------------------
__device__ __forceinline__ uint tf32u(float f) {
    uint u; asm("cvt.rna.tf32.f32 %0, %1;" : "=r"(u) : "f"(f)); return u;
}
__device__ __forceinline__ float tf32f(float f) { return __uint_as_float(tf32u(f)); }

#define MMA_TF32(d, a0, a1, a2, a3, b0, b1) \
    asm("mma.sync.aligned.m16n8k8.row.col.f32.tf32.tf32.f32 " \
        "{%0,%1,%2,%3},{%4,%5,%6,%7},{%8,%9},{%0,%1,%2,%3};" \
        : "+f"(d[0]), "+f"(d[1]), "+f"(d[2]), "+f"(d[3]) \
        : "r"(a0), "r"(a1), "r"(a2), "r"(a3), "r"(b0), "r"(b1))

// ---------------- scratch ---------------------------------------------------
__device__ float g_y1[EMB * HW];
__device__ float g_img[EMB * HW];
__device__ float g_z[EMB * HW];
__device__ float g_bn1[2 * EMB];
__device__ float g_qb[600 * DH * CROP];   // [b][c][row] transposed
__device__ float g_kb[600 * DH * CROP];
__device__ float g_vb[600 * DH * CROP];

// ---------------- conv1 ------------------------------------------------------
__global__ __launch_bounds__(256, 3) void conv1_kernel(const float* __restrict__ x,
                                                       const float* __restrict__ w1,
                                                       float* __restrict__ y1)
{
    extern __shared__ float sm[];
    float* w_s = sm;
    int tid = threadIdx.x;
    for (int idx = tid; idx < CHIN * EMB; idx += 256) {
        int c = idx >> 6, o = idx & 63;
        w_s[idx] = w1[o * CHIN + c];
    }
    __syncthreads();

    int og = tid >> 6, lp = tid & 63;
    int pair = blockIdx.x * 64 + lp;
    if (pair >= NPAIR) return;

    ull acc[16];
#pragma unroll
    for (int k = 0; k < 16; k++) acc[k] = 0ull;

    const float2* xp = (const float2*)x;
    for (int c0 = 0; c0 < CHIN; c0 += 8) {
        float2 xv[8];
#pragma unroll
        for (int u = 0; u < 8; u++)
            xv[u] = xp[(size_t)(c0 + u) * NPAIR + pair];
#pragma unroll
        for (int u = 0; u < 8; u++) {
            ull xx = pack2(xv[u].x, xv[u].x);
            ull yy = pack2(xv[u].y, xv[u].y);
            const ulonglong2* wr = (const ulonglong2*)(w_s + (c0 + u) * EMB + og * 16);
#pragma unroll
            for (int w4 = 0; w4 < 4; w4++) {
                ulonglong2 wv = wr[w4];
                acc[2*w4+0]   = fma2(xx, wv.x, acc[2*w4+0]);
                acc[2*w4+1]   = fma2(xx, wv.y, acc[2*w4+1]);
                acc[8+2*w4+0] = fma2(yy, wv.x, acc[8+2*w4+0]);
                acc[8+2*w4+1] = fma2(yy, wv.y, acc[8+2*w4+1]);
            }
        }
    }
    float2* yp = (float2*)y1;
#pragma unroll
    for (int k = 0; k < 8; k++) {
        float p0l, p0h, p1l, p1h;
        unpack2(acc[k],     p0l, p0h);
        unpack2(acc[8 + k], p1l, p1h);
        int o = og * 16 + 2 * k;
        yp[(size_t)o       * NPAIR + pair] = make_float2(p0l, p1l);
        yp[(size_t)(o + 1) * NPAIR + pair] = make_float2(p0h, p1h);
    }
}

// ---------------- BN1 stats only --------------------------------------------
__global__ __launch_bounds__(1024) void bn_stats_kernel(const float* __restrict__ in,
                                                        const float* __restrict__ gamma,
                                                        const float* __restrict__ beta,
                                                        float* __restrict__ scsh)
{
    int c = blockIdx.x;
    int tid = threadIdx.x;
    const float4* p4 = (const float4*)(in + (size_t)c * HW);

    float s = 0.f, s2 = 0.f;
    for (int i = tid; i < NQUAD; i += 1024) {
        float4 v = p4[i];
        s  += (v.x + v.y) + (v.z + v.w);
        s2 += (v.x*v.x + v.y*v.y) + (v.z*v.z + v.w*v.w);
    }
    __shared__ float rs[32], rs2[32];
#pragma unroll
    for (int off = 16; off; off >>= 1) {
        s  += __shfl_down_sync(0xffffffffu, s, off);
        s2 += __shfl_down_sync(0xffffffffu, s2, off);
    }
    if ((tid & 31) == 0) { rs[tid >> 5] = s; rs2[tid >> 5] = s2; }
    __syncthreads();
    if (tid < 32) {
        float a = rs[tid], a2 = rs2[tid];
#pragma unroll
        for (int off = 16; off; off >>= 1) {
            a  += __shfl_down_sync(0xffffffffu, a, off);
            a2 += __shfl_down_sync(0xffffffffu, a2, off);
        }
        if (tid == 0) {
            const float invn = 1.0f / (float)HW;
            float mean = a * invn;
            float var  = a2 * invn - mean * mean;
            float rstd = rsqrtf(var + 1e-5f);
            float sc = rstd * gamma[c];
            scsh[c]       = sc;
            scsh[EMB + c] = beta[c] - mean * sc;
        }
    }
}

// ---------------- BN2 --------------------------------------------------------
__global__ __launch_bounds__(1024) void bn_kernel(const float* __restrict__ in,
                                                  const float* __restrict__ gamma,
                                                  const float* __restrict__ beta,
                                                  float* __restrict__ out)
{
    int c = blockIdx.x;
    int tid = threadIdx.x;
    const float4* p4 = (const float4*)(in + (size_t)c * HW);

    float s = 0.f, s2 = 0.f;
    for (int i = tid; i < NQUAD; i += 1024) {
        float4 v = p4[i];
        s  += (v.x + v.y) + (v.z + v.w);
        s2 += (v.x*v.x + v.y*v.y) + (v.z*v.z + v.w*v.w);
    }
    __shared__ float rs[32], rs2[32];
    __shared__ float sc_s, sh_s;
#pragma unroll
    for (int off = 16; off; off >>= 1) {
        s  += __shfl_down_sync(0xffffffffu, s, off);
        s2 += __shfl_down_sync(0xffffffffu, s2, off);
    }
    if ((tid & 31) == 0) { rs[tid >> 5] = s; rs2[tid >> 5] = s2; }
    __syncthreads();
    if (tid < 32) {
        float a = rs[tid], a2 = rs2[tid];
#pragma unroll
        for (int off = 16; off; off >>= 1) {
            a  += __shfl_down_sync(0xffffffffu, a, off);
            a2 += __shfl_down_sync(0xffffffffu, a2, off);
        }
        if (tid == 0) {
            const float invn = 1.0f / (float)HW;
            float mean = a * invn;
            float var  = a2 * invn - mean * mean;
            float rstd = rsqrtf(var + 1e-5f);
            float sc = rstd * gamma[c];
            sc_s = sc;
            sh_s = beta[c] - mean * sc;
        }
    }
    __syncthreads();
    float sc = sc_s, sh = sh_s;
    float4* q4 = (float4*)(out + (size_t)c * HW);
    for (int i = tid; i < NQUAD; i += 1024) {
        float4 v = p4[i];
        v.x = fmaxf(fmaf(v.x, sc, sh), 0.f);
        v.y = fmaxf(fmaf(v.y, sc, sh), 0.f);
        v.z = fmaxf(fmaf(v.z, sc, sh), 0.f);
        v.w = fmaxf(fmaf(v.w, sc, sh), 0.f);
        q4[i] = v;
    }
}

// ------- attn_proj: gather + BN1-fold + q/k/v projections -> gmem ------------
// Outputs transposed [b][c][row] so stores are lane-coalesced.
__global__ __launch_bounds__(320, 3) void attn_proj_kernel(
    const float* __restrict__ y1, const float* __restrict__ scsh,
    const float* __restrict__ wq, const float* __restrict__ wkv,
    const int* __restrict__ obj, const int* __restrict__ bg,
    const int* __restrict__ ri,
    float* __restrict__ qb, float* __restrict__ kb, float* __restrict__ vb)
{
    __shared__ float wq_s[1024];   // [c][e]
    __shared__ float wkv_s[2048];
    __shared__ float scs[32], shs[32];

    int b = blockIdx.x, h = b / CROP, i = b % CROP;
    int tid = threadIdx.x;

    for (int idx = tid; idx < 1024; idx += 320) {
        int e = idx & 31, c = idx >> 5;
        wq_s[c * 32 + e] = wq[e * 32 + c];
    }
    for (int idx = tid; idx < 2048; idx += 320) {
        int e = idx & 63, c = idx >> 6;
        wkv_s[c * 64 + e] = wkv[e * 32 + c];
    }
    if (tid < 32) {
        scs[tid] = scsh[h * DH + tid];
        shs[tid] = scsh[EMB + h * DH + tid];
    }
    __syncthreads();

    if (tid < CROP) {
        int r = ri[h * (CROP * CROP) + i * CROP + tid];
        int pos = (i < NHALF) ? obj[r] : bg[r];
        float t[DH];
        const float* xb = y1 + (size_t)(h * DH) * HW + pos;
#pragma unroll
        for (int c = 0; c < DH; c++)
            t[c] = fmaxf(fmaf(xb[(size_t)c * HW], scs[c], shs[c]), 0.f);

        const float scale = 0.17677669529663688110f;
        size_t base = (size_t)b * (DH * CROP) + tid;
#pragma unroll
        for (int e = 0; e < DH; e++) {
            float aq = 0.f, ak = 0.f, av = 0.f;
#pragma unroll
            for (int c = 0; c < DH; c++) {
                float tv = t[c];
                aq += tv * wq_s[c * 32 + e];
                ak += tv * wkv_s[c * 64 + e];
                av += tv * wkv_s[c * 64 + 32 + e];
            }
            qb[base + (size_t)e * CROP] = aq * scale;
            kb[base + (size_t)e * CROP] = ak;
            vb[base + (size_t)e * CROP] = av;
        }
    }
}

// ------- attn_mma: tf32 tensor-core attention per (h,i) ----------------------
// K smem [304][36] fp32 (pad 36 -> conflict-free B-frags), V smem [304][40]
// pre-rounded tf32 with ones-column at col 32 (row-sum via MMA).
// QK uses 3xTF32 split (near-fp32 logits); PV single tf32 with consistent p~.
__global__ __launch_bounds__(320, 2) void attn_mma_kernel(
    const float* __restrict__ qb, const float* __restrict__ kb,
    const float* __restrict__ vb,
    const int* __restrict__ obj, const int* __restrict__ bg,
    const int* __restrict__ ri, float* __restrict__ img)
{
    extern __shared__ float sm[];
    float* Ksm = sm;                       // [304][36]
    float* Vsm = Ksm + 304 * 36;           // [304][40]
    float* Pb  = Vsm + 304 * 40;           // [10][16*12]
    int*   pos_s = (int*)(Pb + 10 * 192);  // [300]

    int b = blockIdx.x, h = b / CROP, i = b % CROP;
    int tid = threadIdx.x, wid = tid >> 5, lane = tid & 31;
    int gid = lane >> 2, tig = lane & 3;

    for (int j = tid; j < CROP; j += 320) {
        int r = ri[h * (CROP * CROP) + i * CROP + j];
        pos_s[j] = (i < NHALF) ? obj[r] : bg[r];
    }
    const float* kbp = kb + (size_t)b * (DH * CROP);
    for (int idx = tid; idx < DH * 75; idx += 320) {
        int c = idx / 75, f4 = idx % 75;
        float4 v = *(const float4*)(kbp + c * CROP + f4 * 4);
        int key = f4 * 4;
        Ksm[(key + 0) * 36 + c] = v.x;
        Ksm[(key + 1) * 36 + c] = v.y;
        Ksm[(key + 2) * 36 + c] = v.z;
        Ksm[(key + 3) * 36 + c] = v.w;
    }
    const float* vbp = vb + (size_t)b * (DH * CROP);
    for (int idx = tid; idx < DH * 75; idx += 320) {
        int c = idx / 75, f4 = idx % 75;
        float4 v = *(const float4*)(vbp + c * CROP + f4 * 4);
        int key = f4 * 4;
        Vsm[(key + 0) * 40 + c] = tf32f(v.x);
        Vsm[(key + 1) * 40 + c] = tf32f(v.y);
        Vsm[(key + 2) * 40 + c] = tf32f(v.z);
        Vsm[(key + 3) * 40 + c] = tf32f(v.w);
    }
    // ones column + tail cols (all 304 rows), ghost rows zero
    for (int idx = tid; idx < 304 * 8; idx += 320) {
        int key = idx / 8, c = 32 + (idx % 8);
        Vsm[key * 40 + c] = (c == 32 && key < CROP) ? 1.0f : 0.f;
    }
    for (int idx = tid; idx < 4 * 36; idx += 320)
        Ksm[(300 + idx / 36) * 36 + (idx % 36)] = 0.f;
    for (int idx = tid; idx < 4 * 32; idx += 320)
        Vsm[(300 + idx / 32) * 40 + (idx % 32)] = 0.f;
    __syncthreads();

    float* myP = Pb + wid * 192;
    const float* qbp = qb + (size_t)b * (DH * CROP);

    for (int p = wid; p < NPANEL; p += 10) {
        int r0 = p * 16 + gid;
        int r1 = r0 + 8;

        // Q fragments (hi/lo split), zero for ghost rows
        uint qhi[16], qlo[16];
#pragma unroll
        for (int k = 0; k < 4; k++) {
            int c0 = 8 * k + tig, c1 = c0 + 4;
            float f0 = (r0 < CROP) ? qbp[(size_t)c0 * CROP + r0] : 0.f;
            float f1 = (r1 < CROP) ? qbp[(size_t)c0 * CROP + r1] : 0.f;
            float f2 = (r0 < CROP) ? qbp[(size_t)c1 * CROP + r0] : 0.f;
            float f3 = (r1 < CROP) ? qbp[(size_t)c1 * CROP + r1] : 0.f;
            uint h0 = tf32u(f0), h1 = tf32u(f1), h2 = tf32u(f2), h3 = tf32u(f3);
            qhi[4*k+0] = h0; qhi[4*k+1] = h1; qhi[4*k+2] = h2; qhi[4*k+3] = h3;
            qlo[4*k+0] = tf32u(f0 - __uint_as_float(h0));
            qlo[4*k+1] = tf32u(f1 - __uint_as_float(h1));
            qlo[4*k+2] = tf32u(f2 - __uint_as_float(h2));
            qlo[4*k+3] = tf32u(f3 - __uint_as_float(h3));
        }

        float O[5][4];
#pragma unroll
        for (int t = 0; t < 5; t++)
#pragma unroll
            for (int c = 0; c < 4; c++) O[t][c] = 0.f;

        for (int s = 0; s < 38; s++) {
            float S[4][4];
#pragma unroll
            for (int k = 0; k < 4; k++)
#pragma unroll
                for (int c = 0; c < 4; c++) S[k][c] = 0.f;

#pragma unroll
            for (int k = 0; k < 4; k++) {
                float f0 = Ksm[(8 * s + gid) * 36 + 8 * k + tig];
                float f1 = Ksm[(8 * s + gid) * 36 + 8 * k + tig + 4];
                uint bh0 = tf32u(f0), bh1 = tf32u(f1);
                uint bl0 = tf32u(f0 - __uint_as_float(bh0));
                uint bl1 = tf32u(f1 - __uint_as_float(bh1));
                MMA_TF32(S[k], qhi[4*k+0], qhi[4*k+1], qhi[4*k+2], qhi[4*k+3], bh0, bh1);
                MMA_TF32(S[k], qhi[4*k+0], qhi[4*k+1], qhi[4*k+2], qhi[4*k+3], bl0, bl1);
                MMA_TF32(S[k], qlo[4*k+0], qlo[4*k+1], qlo[4*k+2], qlo[4*k+3], bh0, bh1);
            }
            float p0 = __expf((S[0][0] + S[1][0]) + (S[2][0] + S[3][0]));
            float p1 = __expf((S[0][1] + S[1][1]) + (S[2][1] + S[3][1]));
            float p2 = __expf((S[0][2] + S[1][2]) + (S[2][2] + S[3][2]));
            float p3 = __expf((S[0][3] + S[1][3]) + (S[2][3] + S[3][3]));
            if (s == 37 && tig >= 2) { p0 = 0.f; p1 = 0.f; p2 = 0.f; p3 = 0.f; }

            *(float2*)(myP + gid * 12 + 2 * tig)       = make_float2(p0, p1);
            *(float2*)(myP + (gid + 8) * 12 + 2 * tig) = make_float2(p2, p3);
            __syncwarp();
            uint pa0 = tf32u(myP[gid * 12 + tig]);
            uint pa1 = tf32u(myP[(gid + 8) * 12 + tig]);
            uint pa2 = tf32u(myP[gid * 12 + tig + 4]);
            uint pa3 = tf32u(myP[(gid + 8) * 12 + tig + 4]);
#pragma unroll
            for (int t = 0; t < 5; t++) {
                uint b0 = __float_as_uint(Vsm[(8 * s + tig) * 40 + 8 * t + gid]);
                uint b1 = __float_as_uint(Vsm[(8 * s + tig + 4) * 40 + 8 * t + gid]);
                MMA_TF32(O[t], pa0, pa1, pa2, pa3, b0, b1);
            }
            __syncwarp();
        }

        // row sums from ones column (tile 4, col 32 -> c0/c2 of lanes tig==0)
        float ss0 = __shfl_sync(0xffffffffu, O[4][0], lane & ~3);
        float ss1 = __shfl_sync(0xffffffffu, O[4][2], lane & ~3);
        float inv0 = 1.0f / ss0;
        float inv1 = 1.0f / ss1;

#pragma unroll
        for (int t = 0; t < 4; t++) {
            int e0 = 8 * t + 2 * tig, e1 = e0 + 1;
            if (r0 < CROP) {
                int m0 = r0 * DH + e0, m1 = r0 * DH + e1;
                int d0 = m0 / CROP, d1 = m1 / CROP;
                img[(size_t)(h * DH + d0) * HW + pos_s[m0 - d0 * CROP]] = O[t][0] * inv0;
                img[(size_t)(h * DH + d1) * HW + pos_s[m1 - d1 * CROP]] = O[t][1] * inv0;
            }
            if (r1 < CROP) {
                int m0 = r1 * DH + e0, m1 = r1 * DH + e1;
                int d0 = m0 / CROP, d1 = m1 / CROP;
                img[(size_t)(h * DH + d0) * HW + pos_s[m0 - d0 * CROP]] = O[t][2] * inv1;
                img[(size_t)(h * DH + d1) * HW + pos_s[m1 - d1 * CROP]] = O[t][3] * inv1;
            }
        }
    }
}

// ------- fuse2a --------------------------------------------------------------
__global__ __launch_bounds__(256, 3) void fuse2a_kernel(const float* __restrict__ img,
                                                        const float* __restrict__ wo,
                                                        const float* __restrict__ bo,
                                                        float* __restrict__ xa)
{
    extern __shared__ float sm[];
    float* wo_s = sm;
    float* bo_s = wo_s + 4096;

    int tid = threadIdx.x;
    for (int idx = tid; idx < 4096; idx += 256) {
        int c = idx >> 6, o = idx & 63;
        wo_s[idx] = wo[o * 64 + c];
    }
    if (tid < 64) bo_s[tid] = bo[tid];
    __syncthreads();

    int og = tid >> 6, lp = tid & 63;
    int pair = blockIdx.x * 64 + lp;
    if (pair >= NPAIR) return;

    ull acc[16];
#pragma unroll
    for (int k = 0; k < 16; k++) acc[k] = 0ull;

    const float2* ip = (const float2*)img;
    for (int c0 = 0; c0 < EMB; c0 += 8) {
        float2 iv[8];
#pragma unroll
        for (int u = 0; u < 8; u++)
            iv[u] = ip[(size_t)(c0 + u) * NPAIR + pair];
#pragma unroll
        for (int u = 0; u < 8; u++) {
            ull xx = pack2(iv[u].x, iv[u].x);
            ull yy = pack2(iv[u].y, iv[u].y);
            const ulonglong2* wr = (const ulonglong2*)(wo_s + (c0 + u) * EMB + og * 16);
#pragma unroll
            for (int w4 = 0; w4 < 4; w4++) {
                ulonglong2 wv = wr[w4];
                acc[2*w4+0]   = fma2(xx, wv.x, acc[2*w4+0]);
                acc[2*w4+1]   = fma2(xx, wv.y, acc[2*w4+1]);
                acc[8+2*w4+0] = fma2(yy, wv.x, acc[8+2*w4+0]);
                acc[8+2*w4+1] = fma2(yy, wv.y, acc[8+2*w4+1]);
            }
        }
    }
    float2* xp = (float2*)xa;
#pragma unroll
    for (int k = 0; k < 8; k++) {
        float p0l, p0h, p1l, p1h;
        unpack2(acc[k],     p0l, p0h);
        unpack2(acc[8 + k], p1l, p1h);
        int o = og * 16 + 2 * k;
        float b0 = bo_s[o], b1 = bo_s[o + 1];
        xp[(size_t)o       * NPAIR + pair] = make_float2(fmaxf(p0l + b0, 0.f), fmaxf(p1l + b0, 0.f));
        xp[(size_t)(o + 1) * NPAIR + pair] = make_float2(fmaxf(p0h + b1, 0.f), fmaxf(p1h + b1, 0.f));
    }
}

// ------- fuse2b --------------------------------------------------------------
__global__ __launch_bounds__(256, 3) void fuse2b_kernel(const float* __restrict__ xa,
                                                        const float* __restrict__ y1,
                                                        const float* __restrict__ scsh,
                                                        const float* __restrict__ w2,
                                                        float* __restrict__ z)
{
    extern __shared__ float sm[];
    float* w2_s = sm;
    float* sc_s = w2_s + 8192;
    float* sh_s = sc_s + 64;

    int tid = threadIdx.x;
    for (int idx = tid; idx < 8192; idx += 256) {
        int cc = idx >> 6, o = idx & 63;
        w2_s[idx] = w2[o * 128 + cc];
    }
    if (tid < 128) {
        if (tid < 64) sc_s[tid] = scsh[tid];
        else          sh_s[tid - 64] = scsh[tid];
    }
    __syncthreads();

    int og = tid >> 6, lp = tid & 63;
    int pair = blockIdx.x * 64 + lp;
    if (pair >= NPAIR) return;

    ull acc[16];
#pragma unroll
    for (int k = 0; k < 16; k++) acc[k] = 0ull;

    const float2* xap = (const float2*)xa;
    for (int c0 = 0; c0 < EMB; c0 += 8) {
        float2 sv[8];
#pragma unroll
        for (int u = 0; u < 8; u++)
            sv[u] = xap[(size_t)(c0 + u) * NPAIR + pair];
#pragma unroll
        for (int u = 0; u < 8; u++) {
            ull xx = pack2(sv[u].x, sv[u].x);
            ull yy = pack2(sv[u].y, sv[u].y);
            const ulonglong2* wr = (const ulonglong2*)(w2_s + (c0 + u) * EMB + og * 16);
#pragma unroll
            for (int w4 = 0; w4 < 4; w4++) {
                ulonglong2 wv = wr[w4];
                acc[2*w4+0]   = fma2(xx, wv.x, acc[2*w4+0]);
                acc[2*w4+1]   = fma2(xx, wv.y, acc[2*w4+1]);
                acc[8+2*w4+0] = fma2(yy, wv.x, acc[8+2*w4+0]);
                acc[8+2*w4+1] = fma2(yy, wv.y, acc[8+2*w4+1]);
            }
        }
    }
    const float2* yp = (const float2*)y1;
    for (int c0 = 0; c0 < EMB; c0 += 8) {
        float2 sv[8];
#pragma unroll
        for (int u = 0; u < 8; u++)
            sv[u] = yp[(size_t)(c0 + u) * NPAIR + pair];
#pragma unroll
        for (int u = 0; u < 8; u++) {
            int cc = c0 + u;
            float scv = sc_s[cc], shv = sh_s[cc];
            float vx = fmaxf(fmaf(sv[u].x, scv, shv), 0.f);
            float vy = fmaxf(fmaf(sv[u].y, scv, shv), 0.f);
            ull xx = pack2(vx, vx);
            ull yy = pack2(vy, vy);
            const ulonglong2* wr = (const ulonglong2*)(w2_s + (EMB + cc) * EMB + og * 16);
#pragma unroll
            for (int w4 = 0; w4 < 4; w4++) {
                ulonglong2 wv = wr[w4];
                acc[2*w4+0]   = fma2(xx, wv.x, acc[2*w4+0]);
                acc[2*w4+1]   = fma2(xx, wv.y, acc[2*w4+1]);
                acc[8+2*w4+0] = fma2(yy, wv.x, acc[8+2*w4+0]);
                acc[8+2*w4+1] = fma2(yy, wv.y, acc[8+2*w4+1]);
            }
        }
    }
    float2* zp = (float2*)z;
#pragma unroll
    for (int k = 0; k < 8; k++) {
        float p0l, p0h, p1l, p1h;
        unpack2(acc[k],     p0l, p0h);
        unpack2(acc[8 + k], p1l, p1h);
        int o = og * 16 + 2 * k;
        zp[(size_t)o       * NPAIR + pair] = make_float2(p0l, p1l);
        zp[(size_t)(o + 1) * NPAIR + pair] = make_float2(p0h, p1h);
    }
}

// ---------------------------------------------------------------------------
extern "C" void kernel_launch(void* const* d_in, const int* in_sizes, int n_in,
                              void* d_out, int out_size)
{
    const float* x   = (const float*)d_in[0];
    const float* w1  = (const float*)d_in[1];
    const float* g1  = (const float*)d_in[2];
    const float* b1  = (const float*)d_in[3];
    const float* wq  = (const float*)d_in[4];
    const float* wkv = (const float*)d_in[5];
    const float* wo  = (const float*)d_in[6];
    const float* bo  = (const float*)d_in[7];
    const float* w2  = (const float*)d_in[8];
    const float* g2  = (const float*)d_in[9];
    const float* b2  = (const float*)d_in[10];
    const int* obj   = (const int*)d_in[11];
    const int* bg    = (const int*)d_in[12];
    const int* ri    = (const int*)d_in[13];
    float* out = (float*)d_out;

    float *y1p, *imgp, *zp, *bn1p, *qbp, *kbp, *vbp;
    cudaGetSymbolAddress((void**)&y1p, g_y1);
    cudaGetSymbolAddress((void**)&imgp, g_img);
    cudaGetSymbolAddress((void**)&zp, g_z);
    cudaGetSymbolAddress((void**)&bn1p, g_bn1);
    cudaGetSymbolAddress((void**)&qbp, g_qb);
    cudaGetSymbolAddress((void**)&kbp, g_kb);
    cudaGetSymbolAddress((void**)&vbp, g_vb);

    const int CONV1_SMEM  = CHIN * EMB * 4;                         // 64 KB
    const int MMA_SMEM    = (304*36 + 304*40 + 10*192 + 300) * 4;   // ~101 KB
    const int FUSE2A_SMEM = (4096 + 64) * 4;
    const int FUSE2B_SMEM = (8192 + 128) * 4;

    cudaFuncSetAttribute(conv1_kernel,    cudaFuncAttributeMaxDynamicSharedMemorySize, CONV1_SMEM);
    cudaFuncSetAttribute(attn_mma_kernel, cudaFuncAttributeMaxDynamicSharedMemorySize, MMA_SMEM);
    cudaFuncSetAttribute(fuse2a_kernel,   cudaFuncAttributeMaxDynamicSharedMemorySize, FUSE2A_SMEM);
    cudaFuncSetAttribute(fuse2b_kernel,   cudaFuncAttributeMaxDynamicSharedMemorySize, FUSE2B_SMEM);

    int grid_pairs = (NPAIR + 63) / 64;  // 704

    conv1_kernel<<<grid_pairs, 256, CONV1_SMEM>>>(x, w1, y1p);
    bn_stats_kernel<<<EMB, 1024>>>(y1p, g1, b1, bn1p);
    attn_proj_kernel<<<2 * CROP, 320>>>(y1p, bn1p, wq, wkv, obj, bg, ri, qbp, kbp, vbp);
    attn_mma_kernel<<<2 * CROP, 320, MMA_SMEM>>>(qbp, kbp, vbp, obj, bg, ri, imgp);
    fuse2a_kernel<<<grid_pairs, 256, FUSE2A_SMEM>>>(imgp, wo, bo, zp);
    fuse2b_kernel<<<grid_pairs, 256, FUSE2B_SMEM>>>(zp, y1p, bn1p, w2, imgp);
    bn_kernel<<<EMB, 1024>>>(imgp, g2, b2, out);
}